// round 4
// baseline (speedup 1.0000x reference)
#include <cuda_runtime.h>
#include <cuda_bf16.h>
#include <math.h>

// Problem constants (fixed dataset)
#define NN 131072      // sentences
#define DD 690         // feature dim (even)
#define D2 345         // DD/2 (float2)
#define CC 53          // classes
#define BB 8192        // bags
#define NSLOT 11       // ceil(D2/32)

// Device scratch (allocation-free rule: __device__ globals)
__device__ float g_prod[CC * DD];          // att ⊙ rel, 143 KB (L1/L2-resident)
__device__ float g_bag[(size_t)BB * DD];   // bag representations, 22.6 MB

// ---------------------------------------------------------------------------
// Kernel 0: prod[c,d] = att[c,d] * rel[c,d]   (vectorized float2)
// ---------------------------------------------------------------------------
__global__ void prod_kernel(const float* __restrict__ rel,
                            const float* __restrict__ att) {
    int i = blockIdx.x * 256 + threadIdx.x;          // float2 index
    if (i < (CC * DD) / 2) {
        const float2* r2 = reinterpret_cast<const float2*>(rel);
        const float2* a2 = reinterpret_cast<const float2*>(att);
        float2 r = r2[i], a = a2[i];
        reinterpret_cast<float2*>(g_prod)[i] = make_float2(r.x * a.x, r.y * a.y);
    }
}

// ---------------------------------------------------------------------------
// Kernel 1: one block per bag, ONE PASS over x (online softmax).
// Each warp streams sentences (warp-per-sentence, stride 8). Per sentence:
//   - x row held in registers (loaded with .cs streaming hint)
//   - logit = x · prod[q]  (prod cached in L1; x doesn't pollute it)
//   - online update: rescale running (d, S) when max improves
// Warps merge (m, d, S) through smem at the end -> g_bag.
// ---------------------------------------------------------------------------
__global__ void __launch_bounds__(256)
bag_attn_kernel(const float* __restrict__ x,
                const int*   __restrict__ q,
                const int*   __restrict__ scope) {
    __shared__ float s_S[8][DD];     // 22080 B: per-warp scaled partial sums
    __shared__ float s_m[8], s_d[8];

    const int b     = blockIdx.x;
    const int start = __ldg(scope + b);
    const int end   = __ldg(scope + b + 1);
    const int tid   = threadIdx.x;
    const int wid   = tid >> 5;
    const int lane  = tid & 31;

    const float2* __restrict__ x2 = reinterpret_cast<const float2*>(x);
    const float2* __restrict__ p2 = reinterpret_cast<const float2*>(g_prod);

    float  m = -INFINITY;            // running max (warp-uniform)
    float  d = 0.f;                  // running denom (warp-uniform)
    float2 S[NSLOT];                 // running weighted sum (distributed over lanes)
    #pragma unroll
    for (int i = 0; i < NSLOT; i++) S[i] = make_float2(0.f, 0.f);

    for (int s = start + wid; s < end; s += 8) {
        const float2* xr = x2 + (size_t)s * D2;
        const float2* pr = p2 + (size_t)__ldg(q + s) * D2;

        // load x row into registers (streaming: keep L1 for prod)
        float2 xa[NSLOT];
        #pragma unroll
        for (int i = 0; i < NSLOT; i++) {
            int dd = lane + i * 32;
            xa[i] = (dd < D2) ? __ldcs(xr + dd) : make_float2(0.f, 0.f);
        }
        // dot with prod row (2 accumulators for ILP)
        float a0 = 0.f, a1 = 0.f;
        #pragma unroll
        for (int i = 0; i < NSLOT; i++) {
            int dd = lane + i * 32;
            if (dd < D2) {
                float2 p = __ldg(pr + dd);
                a0 = fmaf(xa[i].x, p.x, a0);
                a1 = fmaf(xa[i].y, p.y, a1);
            }
        }
        float acc = a0 + a1;
        #pragma unroll
        for (int off = 16; off; off >>= 1)
            acc += __shfl_xor_sync(0xFFFFFFFFu, acc, off);

        // online softmax update (all warp-uniform scalars)
        float mnew  = fmaxf(m, acc);
        float scale = __expf(m - mnew);     // 1 when max unchanged
        float w     = __expf(acc - mnew);
        d = d * scale + w;
        #pragma unroll
        for (int i = 0; i < NSLOT; i++) {
            S[i].x = fmaf(S[i].x, scale, w * xa[i].x);
            S[i].y = fmaf(S[i].y, scale, w * xa[i].y);
        }
        m = mnew;
    }

    if (lane == 0) { s_m[wid] = m; s_d[wid] = d; }
    __syncthreads();

    // every thread computes global max + total denom (8 values, cheap)
    float M = -INFINITY;
    #pragma unroll
    for (int w2 = 0; w2 < 8; w2++) M = fmaxf(M, s_m[w2]);
    float Dt = 0.f;
    #pragma unroll
    for (int w2 = 0; w2 < 8; w2++) Dt += s_d[w2] * __expf(s_m[w2] - M);
    const float inv = 1.f / Dt;

    // write per-warp S scaled to the global max
    const float f = __expf(m - M);          // 0 for empty warps (m = -inf)
    float2* sp = reinterpret_cast<float2*>(s_S[wid]);
    #pragma unroll
    for (int i = 0; i < NSLOT; i++) {
        int dd = lane + i * 32;
        if (dd < D2) sp[dd] = make_float2(S[i].x * f, S[i].y * f);
    }
    __syncthreads();

    // reduce 8 partials, normalize, store bag representation
    for (int dd = tid; dd < DD; dd += 256) {
        float t = 0.f;
        #pragma unroll
        for (int w2 = 0; w2 < 8; w2++) t += s_S[w2][dd];
        g_bag[(size_t)b * DD + dd] = t * inv;
    }
}

// ---------------------------------------------------------------------------
// Kernel 2: logits[b,c] = bag_repre[b,:] · rel[c,:] + bias[c]
// 32 bags per block in smem (88 KB); warp-per-class, shuffle reduction,
// lane-0 statically-indexed stores (no dynamic register indexing).
// ---------------------------------------------------------------------------
#define KBAGS 32
__global__ void __launch_bounds__(256)
out_gemm_kernel(const float* __restrict__ rel,
                const float* __restrict__ bias,
                float* __restrict__ out) {
    __shared__ float s_bag[KBAGS][DD];     // 88320 B

    const int b0   = blockIdx.x * KBAGS;
    const int tid  = threadIdx.x;
    const int wid  = tid >> 5;
    const int lane = tid & 31;

    // load bag tile (contiguous)
    {
        const float2* src = reinterpret_cast<const float2*>(g_bag + (size_t)b0 * DD);
        float2* dst = reinterpret_cast<float2*>(&s_bag[0][0]);
        for (int i = tid; i < KBAGS * D2; i += 256) dst[i] = src[i];
    }
    __syncthreads();

    const float2* __restrict__ rel2 = reinterpret_cast<const float2*>(rel);

    for (int c = wid; c < CC; c += 8) {
        const float2* r2 = rel2 + (size_t)c * D2;
        float acc[KBAGS];
        #pragma unroll
        for (int k = 0; k < KBAGS; k++) acc[k] = 0.f;

        for (int dd = lane; dd < D2; dd += 32) {
            float2 rv = __ldg(r2 + dd);
            #pragma unroll
            for (int k = 0; k < KBAGS; k++) {
                float2 bv = reinterpret_cast<const float2*>(s_bag[k])[dd];
                acc[k] = fmaf(bv.x, rv.x, fmaf(bv.y, rv.y, acc[k]));
            }
        }
        #pragma unroll
        for (int k = 0; k < KBAGS; k++) {
            #pragma unroll
            for (int off = 16; off; off >>= 1)
                acc[k] += __shfl_xor_sync(0xFFFFFFFFu, acc[k], off);
        }
        if (lane == 0) {
            const float bc = __ldg(bias + c);
            #pragma unroll
            for (int k = 0; k < KBAGS; k++)
                out[(size_t)(b0 + k) * CC + c] = acc[k] + bc;
        }
    }
}

// ---------------------------------------------------------------------------
// Entry point. Inputs (metadata order):
//   0: x [N,D] f32   1: relation_weight [C,D] f32   2: attention_weight [C,D] f32
//   3: bias [C] f32  4: attention_query [N] i32     5: scope [B+1] i32
// Output: logits [B,C] f32
// ---------------------------------------------------------------------------
extern "C" void kernel_launch(void* const* d_in, const int* in_sizes, int n_in,
                              void* d_out, int out_size) {
    const float* x    = (const float*)d_in[0];
    const float* rel  = (const float*)d_in[1];
    const float* att  = (const float*)d_in[2];
    const float* bias = (const float*)d_in[3];
    const int*   q    = (const int*)d_in[4];
    const int*   scp  = (const int*)d_in[5];
    float* out = (float*)d_out;

    prod_kernel<<<(CC * DD / 2 + 255) / 256, 256>>>(rel, att);
    bag_attn_kernel<<<BB, 256>>>(x, q, scp);
    out_gemm_kernel<<<BB / KBAGS, 256>>>(rel, bias, out);
    (void)in_sizes; (void)n_in; (void)out_size;
}